// round 1
// baseline (speedup 1.0000x reference)
#include <cuda_runtime.h>
#include <cuda_bf16.h>
#include <math.h>

#define N_OSC 32
#define CONVC 1000.0f

// -------- scratch (no allocations allowed) --------
__device__ float g_xin[2049 + 15];    // [x, timestep]
__device__ float g_h1[4096];
__device__ float g_h2[4096];
__device__ float g_params[2112];
__device__ float g_cpg[64];
__device__ float g_h3[2048];
__device__ float g_h4[2048];

// -------- build input vector: concat(x, timestep) --------
__global__ void build_xin_kernel(const float* __restrict__ x,
                                 const float* __restrict__ ts) {
    int i = blockIdx.x * blockDim.x + threadIdx.x;
    if (i < 2048) g_xin[i] = x[i];
    if (i == 2048) g_xin[2048] = ts[0];
}

// -------- warp-per-row matvec: y = [relu](W @ x + b) --------
// W row-major [rows, cols]. Vectorized float4 path when cols%4==0.
template <bool RELU, bool VEC4>
__global__ void matvec_kernel(const float* __restrict__ W,
                              const float* __restrict__ b,
                              const float* __restrict__ x,
                              float* __restrict__ y,
                              int rows, int cols) {
    int warp = (blockIdx.x * blockDim.x + threadIdx.x) >> 5;
    int lane = threadIdx.x & 31;
    if (warp >= rows) return;

    float s = 0.f;
    if (VEC4) {
        const float4* w4 = reinterpret_cast<const float4*>(W + (size_t)warp * cols);
        const float4* x4 = reinterpret_cast<const float4*>(x);
        int c4 = cols >> 2;
        #pragma unroll 4
        for (int c = lane; c < c4; c += 32) {
            float4 w = w4[c];
            float4 v = x4[c];
            s += w.x * v.x + w.y * v.y + w.z * v.z + w.w * v.w;
        }
    } else {
        const float* w = W + (size_t)warp * cols;
        #pragma unroll 8
        for (int c = lane; c < cols; c += 32) {
            s += w[c] * x[c];
        }
    }
    #pragma unroll
    for (int o = 16; o; o >>= 1) s += __shfl_xor_sync(0xFFFFFFFFu, s, o);

    if (lane == 0) {
        s += b[warp];
        if (RELU) s = fmaxf(s, 0.f);
        y[warp] = s;
    }
}

// -------- CPG ODE, RK4 3/8 rule, single warp (one thread per oscillator) --------
// State layout y = [a(32), ad(32), ph(32)]
// f(y): slot0 = ad ; slot1 = phase_dots(a, ph) ; slot2 = CONV*(CONV/4*(ia-a)-ad)
// (Replicates the reference's slicing EXACTLY, including the post-step
//  ph := new_state[n:2n] read.)
struct S3 { float a, ad, ph; };

__global__ void cpg_ode_kernel(const float* __restrict__ state,
                               const float* __restrict__ ts,
                               float* __restrict__ d_out_state /* 96 floats */) {
    __shared__ float s_cw[N_OSC][N_OSC];
    __shared__ float s_pb[N_OSC][N_OSC];
    int i = threadIdx.x;   // 0..31

    // load coupling rows cooperatively (each thread loads its own row)
    #pragma unroll 4
    for (int j = 0; j < N_OSC; ++j) {
        s_cw[i][j] = g_params[2 * N_OSC + i * N_OSC + j];
        s_pb[i][j] = g_params[2 * N_OSC + N_OSC * N_OSC + i * N_OSC + j];
    }
    float ia  = g_params[i];
    float ifr = g_params[N_OSC + i];
    float h   = ts[0];
    __syncwarp();

    S3 y;
    y.a  = state[i];
    y.ad = state[N_OSC + i];
    y.ph = state[2 * N_OSC + i];

    auto f = [&](S3 v) -> S3 {
        float pdot = ifr;
        #pragma unroll 8
        for (int j = 0; j < N_OSC; ++j) {
            float phj = __shfl_sync(0xFFFFFFFFu, v.ph, j);
            pdot += v.a * s_cw[i][j] * sinf(phj - v.ph - s_pb[i][j]);
        }
        float add = CONVC * (CONVC * 0.25f * (ia - v.a) - v.ad);
        S3 r; r.a = v.ad; r.ad = pdot; r.ph = add;
        return r;
    };
    auto axpy = [](S3 y0, float c, S3 k) -> S3 {
        S3 r; r.a = y0.a + c * k.a; r.ad = y0.ad + c * k.ad; r.ph = y0.ph + c * k.ph;
        return r;
    };

    S3 k1 = f(y);
    S3 k2 = f(axpy(y, h / 3.0f, k1));
    // y + h*(k2 - k1/3)
    S3 t3; t3.a = y.a + h * (k2.a - k1.a / 3.0f);
           t3.ad = y.ad + h * (k2.ad - k1.ad / 3.0f);
           t3.ph = y.ph + h * (k2.ph - k1.ph / 3.0f);
    S3 k3 = f(t3);
    // y + h*(k1 - k2 + k3)
    S3 t4; t4.a = y.a + h * (k1.a - k2.a + k3.a);
           t4.ad = y.ad + h * (k1.ad - k2.ad + k3.ad);
           t4.ph = y.ph + h * (k1.ph - k2.ph + k3.ph);
    S3 k4 = f(t4);

    S3 yn;
    yn.a  = y.a  + h * 0.125f * (k1.a  + 3.0f * (k2.a  + k3.a)  + k4.a);
    yn.ad = y.ad + h * 0.125f * (k1.ad + 3.0f * (k2.ad + k3.ad) + k4.ad);
    yn.ph = y.ph + h * 0.125f * (k1.ph + 3.0f * (k2.ph + k3.ph) + k4.ph);

    // new_state out (tuple element 0)
    d_out_state[i]             = yn.a;
    d_out_state[N_OSC + i]     = yn.ad;
    d_out_state[2 * N_OSC + i] = yn.ph;

    // cpg_out: reference does a = ns[:n], ph = ns[n:2n]  (the ad slot!)
    float aa = yn.a;
    float pp = yn.ad;
    g_cpg[i]         = aa * cosf(pp);
    g_cpg[N_OSC + i] = aa * sinf(pp);
}

extern "C" void kernel_launch(void* const* d_in, const int* in_sizes, int n_in,
                              void* d_out, int out_size) {
    const float* state = (const float*)d_in[0];
    const float* x     = (const float*)d_in[1];
    const float* ts    = (const float*)d_in[2];
    const float* iW0   = (const float*)d_in[3];
    const float* ib0   = (const float*)d_in[4];
    const float* iW1   = (const float*)d_in[5];
    const float* ib1   = (const float*)d_in[6];
    const float* iW2   = (const float*)d_in[7];
    const float* ib2   = (const float*)d_in[8];
    const float* oW0   = (const float*)d_in[9];
    const float* ob0   = (const float*)d_in[10];
    const float* oW1   = (const float*)d_in[11];
    const float* ob1   = (const float*)d_in[12];
    const float* oW2   = (const float*)d_in[13];
    const float* ob2   = (const float*)d_in[14];
    float* out = (float*)d_out;   // [new_state(96), out(1024)]

    float* xin; cudaGetSymbolAddress((void**)&xin, g_xin);
    float* h1;  cudaGetSymbolAddress((void**)&h1,  g_h1);
    float* h2;  cudaGetSymbolAddress((void**)&h2,  g_h2);
    float* pr;  cudaGetSymbolAddress((void**)&pr,  g_params);
    float* cpg; cudaGetSymbolAddress((void**)&cpg, g_cpg);
    float* h3;  cudaGetSymbolAddress((void**)&h3,  g_h3);
    float* h4;  cudaGetSymbolAddress((void**)&h4,  g_h4);

    const int TPB = 256;                 // 8 warps/block
    auto blocks = [](int rows) { return (rows * 32 + 255) / 256; };

    // 1) xin = concat(x, timestep)
    build_xin_kernel<<<(2049 + TPB - 1) / TPB, TPB>>>(x, ts);

    // 2) h1 = relu(iW0 @ xin + ib0)   [4096 x 2049]  (odd cols -> scalar path)
    matvec_kernel<true, false><<<blocks(4096), TPB>>>(iW0, ib0, xin, h1, 4096, 2049);

    // 3) h2 = relu(iW1 @ h1 + ib1)    [4096 x 4096]
    matvec_kernel<true, true><<<blocks(4096), TPB>>>(iW1, ib1, h1, h2, 4096, 4096);

    // 4) params = iW2 @ h2 + ib2      [2112 x 4096]
    matvec_kernel<false, true><<<blocks(2112), TPB>>>(iW2, ib2, h2, pr, 2112, 4096);

    // 5) RK4 step + cpg_out; writes new_state to d_out[0:96]
    cpg_ode_kernel<<<1, 32>>>(state, ts, out);

    // 6) h3 = relu(oW0 @ cpg + ob0)   [2048 x 64]
    matvec_kernel<true, true><<<blocks(2048), TPB>>>(oW0, ob0, cpg, h3, 2048, 64);

    // 7) h4 = relu(oW1 @ h3 + ob1)    [2048 x 2048]
    matvec_kernel<true, true><<<blocks(2048), TPB>>>(oW1, ob1, h3, h4, 2048, 2048);

    // 8) out = oW2 @ h4 + ob2         [1024 x 2048] -> d_out[96:1120]
    matvec_kernel<false, true><<<blocks(1024), TPB>>>(oW2, ob2, h4, out + 96, 1024, 2048);
}

// round 3
// speedup vs baseline: 1.1553x; 1.1553x over previous
#include <cuda_runtime.h>
#include <cuda_bf16.h>
#include <math.h>

#define N_OSC 32
#define CONVC 1000.0f

// -------- scratch (no allocations allowed) --------
__device__ float g_h1[4096];
__device__ float g_h2[4096];
__device__ float g_params[2112];
__device__ float g_cpg[64];
__device__ float g_h3[2048];
__device__ float g_h4[2048];

// ============ block-per-row matvec, compile-time col count ============
// W row-major [rows, 4*C4]. One block (256 thr) per row. Fully unrolled.
template <bool RELU, int C4>
__global__ __launch_bounds__(256) void matvec_b(const float* __restrict__ W,
                                                const float* __restrict__ b,
                                                const float* __restrict__ x,
                                                float* __restrict__ y) {
    int row = blockIdx.x;
    const float4* __restrict__ w4 = reinterpret_cast<const float4*>(W) + (size_t)row * C4;
    const float4* __restrict__ x4 = reinterpret_cast<const float4*>(x);

    float s = 0.f;
    #pragma unroll
    for (int k = 0; k < C4 / 256; ++k) {
        int c = threadIdx.x + k * 256;
        float4 w = w4[c];
        float4 v = x4[c];
        s += w.x * v.x + w.y * v.y + w.z * v.z + w.w * v.w;
    }

    // reduce 256 -> 1
    #pragma unroll
    for (int o = 16; o; o >>= 1) s += __shfl_xor_sync(0xFFFFFFFFu, s, o);
    __shared__ float red[8];
    if ((threadIdx.x & 31) == 0) red[threadIdx.x >> 5] = s;
    __syncthreads();
    if (threadIdx.x < 8) {
        float v = red[threadIdx.x];
        #pragma unroll
        for (int o = 4; o; o >>= 1) v += __shfl_xor_sync(0xFFu, v, o);
        if (threadIdx.x == 0) {
            v += b[row];
            if (RELU) v = fmaxf(v, 0.f);
            y[row] = v;
        }
    }
}

// ============ layer 1: cols = 2049 = 2048 (from x) + 1 (timestep) ============
// Row stride 2049 floats -> only 4B alignment; scalar loads, fully unrolled.
__global__ __launch_bounds__(256) void matvec_l1(const float* __restrict__ W,
                                                 const float* __restrict__ b,
                                                 const float* __restrict__ x,
                                                 const float* __restrict__ ts,
                                                 float* __restrict__ y) {
    int row = blockIdx.x;
    const float* __restrict__ w = W + (size_t)row * 2049;

    float s = 0.f;
    #pragma unroll
    for (int k = 0; k < 8; ++k) {
        int c = threadIdx.x + k * 256;
        s += w[c] * x[c];
    }
    if (threadIdx.x == 0) s += w[2048] * ts[0];

    #pragma unroll
    for (int o = 16; o; o >>= 1) s += __shfl_xor_sync(0xFFFFFFFFu, s, o);
    __shared__ float red[8];
    if ((threadIdx.x & 31) == 0) red[threadIdx.x >> 5] = s;
    __syncthreads();
    if (threadIdx.x < 8) {
        float v = red[threadIdx.x];
        #pragma unroll
        for (int o = 4; o; o >>= 1) v += __shfl_xor_sync(0xFFu, v, o);
        if (threadIdx.x == 0) {
            v += b[row];
            y[row] = fmaxf(v, 0.f);
        }
    }
}

// ============ small layer [2048 x 64]: warp-per-row (lanes 0-15 active) ============
__global__ void matvec_small64(const float* __restrict__ W,
                               const float* __restrict__ b,
                               const float* __restrict__ x,
                               float* __restrict__ y, int rows) {
    int warp = (blockIdx.x * blockDim.x + threadIdx.x) >> 5;
    int lane = threadIdx.x & 31;
    if (warp >= rows) return;
    float s = 0.f;
    if (lane < 16) {
        float4 w = reinterpret_cast<const float4*>(W + (size_t)warp * 64)[lane];
        float4 v = reinterpret_cast<const float4*>(x)[lane];
        s = w.x * v.x + w.y * v.y + w.z * v.z + w.w * v.w;
    }
    #pragma unroll
    for (int o = 8; o; o >>= 1) s += __shfl_xor_sync(0xFFFFFFFFu, s, o);
    if (lane == 0) y[warp] = fmaxf(s + b[warp], 0.f);
}

// ============ CPG ODE, RK4 3/8 rule, single warp ============
// Replicates the reference slicing EXACTLY (phase_dots integrate into the
// a_dot slot; post-step ph is read from that slot).
struct S3 { float a, ad, ph; };

__global__ void cpg_ode_kernel(const float* __restrict__ state,
                               const float* __restrict__ ts,
                               float* __restrict__ d_out_state /* 96 floats */) {
    __shared__ float s_cw[N_OSC][N_OSC];
    __shared__ float s_pb[N_OSC][N_OSC];
    int i = threadIdx.x;   // 0..31

    #pragma unroll 4
    for (int j = 0; j < N_OSC; ++j) {
        s_cw[i][j] = g_params[2 * N_OSC + i * N_OSC + j];
        s_pb[i][j] = g_params[2 * N_OSC + N_OSC * N_OSC + i * N_OSC + j];
    }
    float ia  = g_params[i];
    float ifr = g_params[N_OSC + i];
    float h   = ts[0];
    __syncwarp();

    S3 y;
    y.a  = state[i];
    y.ad = state[N_OSC + i];
    y.ph = state[2 * N_OSC + i];

    auto f = [&](S3 v) -> S3 {
        float pdot = ifr;
        #pragma unroll 8
        for (int j = 0; j < N_OSC; ++j) {
            float phj = __shfl_sync(0xFFFFFFFFu, v.ph, j);
            pdot += v.a * s_cw[i][j] * sinf(phj - v.ph - s_pb[i][j]);
        }
        float add = CONVC * (CONVC * 0.25f * (ia - v.a) - v.ad);
        S3 r; r.a = v.ad; r.ad = pdot; r.ph = add;
        return r;
    };

    S3 k1 = f(y);
    S3 t2; t2.a = y.a + h * k1.a / 3.0f;
           t2.ad = y.ad + h * k1.ad / 3.0f;
           t2.ph = y.ph + h * k1.ph / 3.0f;
    S3 k2 = f(t2);
    S3 t3; t3.a = y.a + h * (k2.a - k1.a / 3.0f);
           t3.ad = y.ad + h * (k2.ad - k1.ad / 3.0f);
           t3.ph = y.ph + h * (k2.ph - k1.ph / 3.0f);
    S3 k3 = f(t3);
    S3 t4; t4.a = y.a + h * (k1.a - k2.a + k3.a);
           t4.ad = y.ad + h * (k1.ad - k2.ad + k3.ad);
           t4.ph = y.ph + h * (k1.ph - k2.ph + k3.ph);
    S3 k4 = f(t4);

    S3 yn;
    yn.a  = y.a  + h * 0.125f * (k1.a  + 3.0f * (k2.a  + k3.a)  + k4.a);
    yn.ad = y.ad + h * 0.125f * (k1.ad + 3.0f * (k2.ad + k3.ad) + k4.ad);
    yn.ph = y.ph + h * 0.125f * (k1.ph + 3.0f * (k2.ph + k3.ph) + k4.ph);

    d_out_state[i]             = yn.a;
    d_out_state[N_OSC + i]     = yn.ad;
    d_out_state[2 * N_OSC + i] = yn.ph;

    float aa = yn.a;
    float pp = yn.ad;   // reference reads ns[n:2n] as "ph"
    g_cpg[i]         = aa * cosf(pp);
    g_cpg[N_OSC + i] = aa * sinf(pp);
}

extern "C" void kernel_launch(void* const* d_in, const int* in_sizes, int n_in,
                              void* d_out, int out_size) {
    const float* state = (const float*)d_in[0];
    const float* x     = (const float*)d_in[1];
    const float* ts    = (const float*)d_in[2];
    const float* iW0   = (const float*)d_in[3];
    const float* ib0   = (const float*)d_in[4];
    const float* iW1   = (const float*)d_in[5];
    const float* ib1   = (const float*)d_in[6];
    const float* iW2   = (const float*)d_in[7];
    const float* ib2   = (const float*)d_in[8];
    const float* oW0   = (const float*)d_in[9];
    const float* ob0   = (const float*)d_in[10];
    const float* oW1   = (const float*)d_in[11];
    const float* ob1   = (const float*)d_in[12];
    const float* oW2   = (const float*)d_in[13];
    const float* ob2   = (const float*)d_in[14];
    float* out = (float*)d_out;   // [new_state(96), out(1024)]

    float* h1;  cudaGetSymbolAddress((void**)&h1,  g_h1);
    float* h2;  cudaGetSymbolAddress((void**)&h2,  g_h2);
    float* pr;  cudaGetSymbolAddress((void**)&pr,  g_params);
    float* cpg; cudaGetSymbolAddress((void**)&cpg, g_cpg);
    float* h3;  cudaGetSymbolAddress((void**)&h3,  g_h3);
    float* h4;  cudaGetSymbolAddress((void**)&h4,  g_h4);

    // 1) h1 = relu(iW0 @ [x, ts] + ib0)   [4096 x 2049]
    matvec_l1<<<4096, 256>>>(iW0, ib0, x, ts, h1);

    // 2) h2 = relu(iW1 @ h1 + ib1)        [4096 x 4096]
    matvec_b<true, 1024><<<4096, 256>>>(iW1, ib1, h1, h2);

    // 3) params = iW2 @ h2 + ib2          [2112 x 4096]
    matvec_b<false, 1024><<<2112, 256>>>(iW2, ib2, h2, pr);

    // 4) RK4 step + cpg_out; writes new_state to d_out[0:96]
    cpg_ode_kernel<<<1, 32>>>(state, ts, out);

    // 5) h3 = relu(oW0 @ cpg + ob0)       [2048 x 64]
    matvec_small64<<<(2048 * 32) / 256, 256>>>(oW0, ob0, cpg, h3, 2048);

    // 6) h4 = relu(oW1 @ h3 + ob1)        [2048 x 2048]
    matvec_b<true, 512><<<2048, 256>>>(oW1, ob1, h3, h4);

    // 7) out = oW2 @ h4 + ob2             [1024 x 2048] -> d_out[96:1120]
    matvec_b<false, 512><<<1024, 256>>>(oW2, ob2, h4, out + 96);
}

// round 4
// speedup vs baseline: 1.5497x; 1.3414x over previous
#include <cuda_runtime.h>
#include <cuda_bf16.h>
#include <math.h>

#define N_OSC 32
#define CONVC 1000.0f

// -------- scratch (no allocations allowed) --------
__device__ float g_h1[4096];
__device__ float g_h2[4096];
__device__ float g_params[2112];
__device__ float g_cpg[64];
__device__ float g_h3[2048];
__device__ float g_h4[2048];

// ============ block-per-row matvec, compile-time col count ============
template <bool RELU, int C4>
__global__ __launch_bounds__(256) void matvec_b(const float* __restrict__ W,
                                                const float* __restrict__ b,
                                                const float* __restrict__ x,
                                                float* __restrict__ y) {
    int row = blockIdx.x;
    const float4* __restrict__ w4 = reinterpret_cast<const float4*>(W) + (size_t)row * C4;
    const float4* __restrict__ x4 = reinterpret_cast<const float4*>(x);

    float s = 0.f;
    #pragma unroll
    for (int k = 0; k < C4 / 256; ++k) {
        int c = threadIdx.x + k * 256;
        float4 w = w4[c];
        float4 v = x4[c];
        s += w.x * v.x + w.y * v.y + w.z * v.z + w.w * v.w;
    }

    #pragma unroll
    for (int o = 16; o; o >>= 1) s += __shfl_xor_sync(0xFFFFFFFFu, s, o);
    __shared__ float red[8];
    if ((threadIdx.x & 31) == 0) red[threadIdx.x >> 5] = s;
    __syncthreads();
    if (threadIdx.x < 8) {
        float v = red[threadIdx.x];
        #pragma unroll
        for (int o = 4; o; o >>= 1) v += __shfl_xor_sync(0xFFu, v, o);
        if (threadIdx.x == 0) {
            v += b[row];
            if (RELU) v = fmaxf(v, 0.f);
            y[row] = v;
        }
    }
}

// ============ layer 1: cols = 2049 (2048 from x + timestep) ============
__global__ __launch_bounds__(256) void matvec_l1(const float* __restrict__ W,
                                                 const float* __restrict__ b,
                                                 const float* __restrict__ x,
                                                 const float* __restrict__ ts,
                                                 float* __restrict__ y) {
    int row = blockIdx.x;
    const float* __restrict__ w = W + (size_t)row * 2049;

    float s = 0.f;
    #pragma unroll
    for (int k = 0; k < 8; ++k) {
        int c = threadIdx.x + k * 256;
        s += w[c] * x[c];
    }
    if (threadIdx.x == 0) s += w[2048] * ts[0];

    #pragma unroll
    for (int o = 16; o; o >>= 1) s += __shfl_xor_sync(0xFFFFFFFFu, s, o);
    __shared__ float red[8];
    if ((threadIdx.x & 31) == 0) red[threadIdx.x >> 5] = s;
    __syncthreads();
    if (threadIdx.x < 8) {
        float v = red[threadIdx.x];
        #pragma unroll
        for (int o = 4; o; o >>= 1) v += __shfl_xor_sync(0xFFu, v, o);
        if (threadIdx.x == 0) {
            v += b[row];
            y[row] = fmaxf(v, 0.f);
        }
    }
}

// ============ small layer [2048 x 64]: warp-per-row ============
__global__ void matvec_small64(const float* __restrict__ W,
                               const float* __restrict__ b,
                               const float* __restrict__ x,
                               float* __restrict__ y, int rows) {
    int warp = (blockIdx.x * blockDim.x + threadIdx.x) >> 5;
    int lane = threadIdx.x & 31;
    if (warp >= rows) return;
    float s = 0.f;
    if (lane < 16) {
        float4 w = reinterpret_cast<const float4*>(W + (size_t)warp * 64)[lane];
        float4 v = reinterpret_cast<const float4*>(x)[lane];
        s = w.x * v.x + w.y * v.y + w.z * v.z + w.w * v.w;
    }
    #pragma unroll
    for (int o = 8; o; o >>= 1) s += __shfl_xor_sync(0xFFFFFFFFu, s, o);
    if (lane == 0) y[warp] = fmaxf(s + b[warp], 0.f);
}

// ============ CPG ODE, RK4 3/8 rule — PARALLEL version ============
// 32 warps: warp i <-> oscillator i, lane j <-> coupling term j.
// Eval-point state in shared; cw/pb rows in registers (lane j of warp i
// holds cw[i][j], pb[i][j]).
// Replicates reference slicing exactly: phase_dots go into the a_dot slot,
// and post-step "ph" is read from that slot for cpg_out.
__global__ __launch_bounds__(1024) void cpg_ode_kernel(
        const float* __restrict__ state,
        const float* __restrict__ ts,
        float* __restrict__ d_out_state /* 96 floats */) {
    __shared__ float s_a[N_OSC], s_ad[N_OSC], s_ph[N_OSC];

    int i = threadIdx.x >> 5;   // oscillator (warp) index
    int j = threadIdx.x & 31;   // coupling term (lane) index

    // per-lane coupling params (coalesced per warp)
    float cw_ij = g_params[2 * N_OSC + i * N_OSC + j];
    float pb_ij = g_params[2 * N_OSC + N_OSC * N_OSC + i * N_OSC + j];

    float h = ts[0];

    // lane-0-owned oscillator params / state
    float ia = 0.f, ifr = 0.f, ya = 0.f, yad = 0.f, yph = 0.f;
    if (j == 0) {
        ia  = g_params[i];
        ifr = g_params[N_OSC + i];
        ya  = state[i];
        yad = state[N_OSC + i];
        yph = state[2 * N_OSC + i];
        s_a[i]  = ya;
        s_ad[i] = yad;
        s_ph[i] = yph;
    }
    __syncthreads();

    float k1a, k1ad, k1ph, k2a, k2ad, k2ph, k3a, k3ad, k3ph, k4a, k4ad, k4ph;

    // one RK4 stage: evaluate f at shared state; lane 0 of warp i gets k
    auto stage = [&](float& ka, float& kad, float& kph) {
        float phi = s_ph[i];           // broadcast read
        float phj = s_ph[j];           // conflict-free (lane j -> bank j)
        float t = cw_ij * sinf(phj - phi - pb_ij);
        #pragma unroll
        for (int o = 16; o; o >>= 1) t += __shfl_xor_sync(0xFFFFFFFFu, t, o);
        if (j == 0) {
            float ea  = s_a[i];
            float ead = s_ad[i];
            kad = ifr + ea * t;                                // phase_dots
            ka  = ead;                                         // a_dot
            kph = CONVC * (CONVC * 0.25f * (ia - ea) - ead);   // a_dd
        }
    };
    // write next eval point (lane 0 only), then barrier
    auto set_eval = [&](float na, float nad, float nph) {
        if (j == 0) { s_a[i] = na; s_ad[i] = nad; s_ph[i] = nph; }
    };

    // k1 at y
    stage(k1a, k1ad, k1ph);
    __syncthreads();
    set_eval(ya + h * k1a / 3.0f, yad + h * k1ad / 3.0f, yph + h * k1ph / 3.0f);
    __syncthreads();

    // k2 at y + h*k1/3
    stage(k2a, k2ad, k2ph);
    __syncthreads();
    set_eval(ya + h * (k2a - k1a / 3.0f),
             yad + h * (k2ad - k1ad / 3.0f),
             yph + h * (k2ph - k1ph / 3.0f));
    __syncthreads();

    // k3 at y + h*(k2 - k1/3)
    stage(k3a, k3ad, k3ph);
    __syncthreads();
    set_eval(ya + h * (k1a - k2a + k3a),
             yad + h * (k1ad - k2ad + k3ad),
             yph + h * (k1ph - k2ph + k3ph));
    __syncthreads();

    // k4 at y + h*(k1 - k2 + k3)
    stage(k4a, k4ad, k4ph);

    if (j == 0) {
        float yna  = ya  + h * 0.125f * (k1a  + 3.0f * (k2a  + k3a)  + k4a);
        float ynad = yad + h * 0.125f * (k1ad + 3.0f * (k2ad + k3ad) + k4ad);
        float ynph = yph + h * 0.125f * (k1ph + 3.0f * (k2ph + k3ph) + k4ph);

        d_out_state[i]             = yna;
        d_out_state[N_OSC + i]     = ynad;
        d_out_state[2 * N_OSC + i] = ynph;

        // reference reads ns[:n] as a and ns[n:2n] (the a_dot slot) as ph
        g_cpg[i]         = yna * cosf(ynad);
        g_cpg[N_OSC + i] = yna * sinf(ynad);
    }
}

extern "C" void kernel_launch(void* const* d_in, const int* in_sizes, int n_in,
                              void* d_out, int out_size) {
    const float* state = (const float*)d_in[0];
    const float* x     = (const float*)d_in[1];
    const float* ts    = (const float*)d_in[2];
    const float* iW0   = (const float*)d_in[3];
    const float* ib0   = (const float*)d_in[4];
    const float* iW1   = (const float*)d_in[5];
    const float* ib1   = (const float*)d_in[6];
    const float* iW2   = (const float*)d_in[7];
    const float* ib2   = (const float*)d_in[8];
    const float* oW0   = (const float*)d_in[9];
    const float* ob0   = (const float*)d_in[10];
    const float* oW1   = (const float*)d_in[11];
    const float* ob1   = (const float*)d_in[12];
    const float* oW2   = (const float*)d_in[13];
    const float* ob2   = (const float*)d_in[14];
    float* out = (float*)d_out;   // [new_state(96), out(1024)]

    float* h1;  cudaGetSymbolAddress((void**)&h1,  g_h1);
    float* h2;  cudaGetSymbolAddress((void**)&h2,  g_h2);
    float* pr;  cudaGetSymbolAddress((void**)&pr,  g_params);
    float* cpg; cudaGetSymbolAddress((void**)&cpg, g_cpg);
    float* h3;  cudaGetSymbolAddress((void**)&h3,  g_h3);
    float* h4;  cudaGetSymbolAddress((void**)&h4,  g_h4);

    // 1) h1 = relu(iW0 @ [x, ts] + ib0)   [4096 x 2049]
    matvec_l1<<<4096, 256>>>(iW0, ib0, x, ts, h1);

    // 2) h2 = relu(iW1 @ h1 + ib1)        [4096 x 4096]
    matvec_b<true, 1024><<<4096, 256>>>(iW1, ib1, h1, h2);

    // 3) params = iW2 @ h2 + ib2          [2112 x 4096]
    matvec_b<false, 1024><<<2112, 256>>>(iW2, ib2, h2, pr);

    // 4) RK4 step + cpg_out; writes new_state to d_out[0:96]
    cpg_ode_kernel<<<1, 1024>>>(state, ts, out);

    // 5) h3 = relu(oW0 @ cpg + ob0)       [2048 x 64]
    matvec_small64<<<(2048 * 32) / 256, 256>>>(oW0, ob0, cpg, h3, 2048);

    // 6) h4 = relu(oW1 @ h3 + ob1)        [2048 x 2048]
    matvec_b<true, 512><<<2048, 256>>>(oW1, ob1, h3, h4);

    // 7) out = oW2 @ h4 + ob2             [1024 x 2048] -> d_out[96:1120]
    matvec_b<false, 512><<<1024, 256>>>(oW2, ob2, h4, out + 96);
}

// round 5
// speedup vs baseline: 1.7536x; 1.1316x over previous
#include <cuda_runtime.h>
#include <cuda_bf16.h>
#include <math.h>

#define N_OSC 32
#define CONVC 1000.0f

// -------- scratch (no allocations allowed) --------
__device__ float g_h1[4096];
__device__ float g_h2[4096];
__device__ float g_params[2112];
__device__ float g_cpg[64];
__device__ float g_h3[2048];
__device__ float g_h4[2048];

// ============ block-per-row matvec with PDL weight prefetch ============
// W row-major [rows, 4*C4]. One block (256 thr) per row.
// Weights are loaded into registers BEFORE cudaGridDependencySynchronize()
// so the weight HBM traffic overlaps the predecessor kernel.
template <bool RELU, int C4>
__global__ __launch_bounds__(256) void matvec_b(const float* __restrict__ W,
                                                const float* __restrict__ b,
                                                const float* __restrict__ x,
                                                float* __restrict__ y) {
    int row = blockIdx.x;
    const float4* __restrict__ w4 = reinterpret_cast<const float4*>(W) + (size_t)row * C4;
    const float4* __restrict__ x4 = reinterpret_cast<const float4*>(x);

    float4 wreg[C4 / 256];
    #pragma unroll
    for (int k = 0; k < C4 / 256; ++k)
        wreg[k] = w4[threadIdx.x + k * 256];
    float bias = (threadIdx.x == 0) ? b[row] : 0.f;

    cudaGridDependencySynchronize();   // wait for predecessor's x

    float s = 0.f;
    #pragma unroll
    for (int k = 0; k < C4 / 256; ++k) {
        float4 v = x4[threadIdx.x + k * 256];
        s += wreg[k].x * v.x + wreg[k].y * v.y + wreg[k].z * v.z + wreg[k].w * v.w;
    }

    #pragma unroll
    for (int o = 16; o; o >>= 1) s += __shfl_xor_sync(0xFFFFFFFFu, s, o);
    __shared__ float red[8];
    if ((threadIdx.x & 31) == 0) red[threadIdx.x >> 5] = s;
    __syncthreads();
    if (threadIdx.x < 8) {
        float v = red[threadIdx.x];
        #pragma unroll
        for (int o = 4; o; o >>= 1) v += __shfl_xor_sync(0xFFu, v, o);
        if (threadIdx.x == 0) {
            v += bias;
            if (RELU) v = fmaxf(v, 0.f);
            y[row] = v;
        }
    }
}

// ============ layer 1: cols = 2049 (2048 from x + timestep) ============
// First kernel in the chain: no PDL sync needed (inputs are harness buffers).
__global__ __launch_bounds__(256) void matvec_l1(const float* __restrict__ W,
                                                 const float* __restrict__ b,
                                                 const float* __restrict__ x,
                                                 const float* __restrict__ ts,
                                                 float* __restrict__ y) {
    int row = blockIdx.x;
    const float* __restrict__ w = W + (size_t)row * 2049;

    float s = 0.f;
    #pragma unroll
    for (int k = 0; k < 8; ++k) {
        int c = threadIdx.x + k * 256;
        s += w[c] * x[c];
    }
    if (threadIdx.x == 0) s += w[2048] * ts[0];

    #pragma unroll
    for (int o = 16; o; o >>= 1) s += __shfl_xor_sync(0xFFFFFFFFu, s, o);
    __shared__ float red[8];
    if ((threadIdx.x & 31) == 0) red[threadIdx.x >> 5] = s;
    __syncthreads();
    if (threadIdx.x < 8) {
        float v = red[threadIdx.x];
        #pragma unroll
        for (int o = 4; o; o >>= 1) v += __shfl_xor_sync(0xFFu, v, o);
        if (threadIdx.x == 0) {
            v += b[row];
            y[row] = fmaxf(v, 0.f);
        }
    }
}

// ============ small layer [2048 x 64]: warp-per-row, PDL prefetch ============
__global__ void matvec_small64(const float* __restrict__ W,
                               const float* __restrict__ b,
                               const float* __restrict__ x,
                               float* __restrict__ y, int rows) {
    int warp = (blockIdx.x * blockDim.x + threadIdx.x) >> 5;
    int lane = threadIdx.x & 31;

    float4 w = make_float4(0.f, 0.f, 0.f, 0.f);
    float bias = 0.f;
    if (warp < rows) {
        if (lane < 16)
            w = reinterpret_cast<const float4*>(W + (size_t)warp * 64)[lane];
        if (lane == 0) bias = b[warp];
    }

    cudaGridDependencySynchronize();   // wait for cpg

    if (warp >= rows) return;
    float s = 0.f;
    if (lane < 16) {
        float4 v = reinterpret_cast<const float4*>(x)[lane];
        s = w.x * v.x + w.y * v.y + w.z * v.z + w.w * v.w;
    }
    #pragma unroll
    for (int o = 8; o; o >>= 1) s += __shfl_xor_sync(0xFFFFFFFFu, s, o);
    if (lane == 0) y[warp] = fmaxf(s + bias, 0.f);
}

// ============ CPG ODE, RK4 3/8 rule — parallel, fast sin ============
// 32 warps: warp i <-> oscillator i, lane j <-> coupling term j.
// Replicates reference slicing exactly (phase_dots in the a_dot slot;
// post-step "ph" read from that slot for cpg_out).
__global__ __launch_bounds__(1024) void cpg_ode_kernel(
        const float* __restrict__ state,
        const float* __restrict__ ts,
        float* __restrict__ d_out_state /* 96 floats */) {
    __shared__ float s_a[N_OSC], s_ad[N_OSC], s_ph[N_OSC];

    int i = threadIdx.x >> 5;   // oscillator (warp) index
    int j = threadIdx.x & 31;   // coupling term (lane) index

    // independent inputs: prefetch before dependency sync
    float h = ts[0];
    float ya = 0.f, yad = 0.f, yph = 0.f;
    if (j == 0) {
        ya  = state[i];
        yad = state[N_OSC + i];
        yph = state[2 * N_OSC + i];
    }

    cudaGridDependencySynchronize();   // wait for g_params

    float cw_ij = g_params[2 * N_OSC + i * N_OSC + j];
    float pb_ij = g_params[2 * N_OSC + N_OSC * N_OSC + i * N_OSC + j];

    float ia = 0.f, ifr = 0.f;
    if (j == 0) {
        ia  = g_params[i];
        ifr = g_params[N_OSC + i];
        s_a[i]  = ya;
        s_ad[i] = yad;
        s_ph[i] = yph;
    }
    __syncthreads();

    float k1a, k1ad, k1ph, k2a, k2ad, k2ph, k3a, k3ad, k3ph, k4a, k4ad, k4ph;

    auto stage = [&](float& ka, float& kad, float& kph) {
        float phi = s_ph[i];
        float phj = s_ph[j];
        float t = cw_ij * __sinf(phj - phi - pb_ij);
        #pragma unroll
        for (int o = 16; o; o >>= 1) t += __shfl_xor_sync(0xFFFFFFFFu, t, o);
        if (j == 0) {
            float ea  = s_a[i];
            float ead = s_ad[i];
            kad = ifr + ea * t;                                // phase_dots
            ka  = ead;                                         // a_dot
            kph = CONVC * (CONVC * 0.25f * (ia - ea) - ead);   // a_dd
        }
    };
    auto set_eval = [&](float na, float nad, float nph) {
        if (j == 0) { s_a[i] = na; s_ad[i] = nad; s_ph[i] = nph; }
    };

    stage(k1a, k1ad, k1ph);
    __syncthreads();
    set_eval(ya + h * k1a / 3.0f, yad + h * k1ad / 3.0f, yph + h * k1ph / 3.0f);
    __syncthreads();

    stage(k2a, k2ad, k2ph);
    __syncthreads();
    set_eval(ya + h * (k2a - k1a / 3.0f),
             yad + h * (k2ad - k1ad / 3.0f),
             yph + h * (k2ph - k1ph / 3.0f));
    __syncthreads();

    stage(k3a, k3ad, k3ph);
    __syncthreads();
    set_eval(ya + h * (k1a - k2a + k3a),
             yad + h * (k1ad - k2ad + k3ad),
             yph + h * (k1ph - k2ph + k3ph));
    __syncthreads();

    stage(k4a, k4ad, k4ph);

    if (j == 0) {
        float yna  = ya  + h * 0.125f * (k1a  + 3.0f * (k2a  + k3a)  + k4a);
        float ynad = yad + h * 0.125f * (k1ad + 3.0f * (k2ad + k3ad) + k4ad);
        float ynph = yph + h * 0.125f * (k1ph + 3.0f * (k2ph + k3ph) + k4ph);

        d_out_state[i]             = yna;
        d_out_state[N_OSC + i]     = ynad;
        d_out_state[2 * N_OSC + i] = ynph;

        // reference reads ns[:n] as a and ns[n:2n] (the a_dot slot) as ph
        g_cpg[i]         = yna * __cosf(ynad);
        g_cpg[N_OSC + i] = yna * __sinf(ynad);
    }
}

// -------- launch helper with PDL attribute --------
template <typename K, typename... Args>
static void launch_pdl(K kernel, dim3 grid, dim3 block, Args... args) {
    cudaLaunchConfig_t cfg = {};
    cfg.gridDim = grid;
    cfg.blockDim = block;
    cudaLaunchAttribute attr[1];
    attr[0].id = cudaLaunchAttributeProgrammaticStreamSerialization;
    attr[0].val.programmaticStreamSerializationAllowed = 1;
    cfg.attrs = attr;
    cfg.numAttrs = 1;
    cudaLaunchKernelEx(&cfg, kernel, args...);
}

extern "C" void kernel_launch(void* const* d_in, const int* in_sizes, int n_in,
                              void* d_out, int out_size) {
    const float* state = (const float*)d_in[0];
    const float* x     = (const float*)d_in[1];
    const float* ts    = (const float*)d_in[2];
    const float* iW0   = (const float*)d_in[3];
    const float* ib0   = (const float*)d_in[4];
    const float* iW1   = (const float*)d_in[5];
    const float* ib1   = (const float*)d_in[6];
    const float* iW2   = (const float*)d_in[7];
    const float* ib2   = (const float*)d_in[8];
    const float* oW0   = (const float*)d_in[9];
    const float* ob0   = (const float*)d_in[10];
    const float* oW1   = (const float*)d_in[11];
    const float* ob1   = (const float*)d_in[12];
    const float* oW2   = (const float*)d_in[13];
    const float* ob2   = (const float*)d_in[14];
    float* out = (float*)d_out;   // [new_state(96), out(1024)]

    float* h1;  cudaGetSymbolAddress((void**)&h1,  g_h1);
    float* h2;  cudaGetSymbolAddress((void**)&h2,  g_h2);
    float* pr;  cudaGetSymbolAddress((void**)&pr,  g_params);
    float* cpg; cudaGetSymbolAddress((void**)&cpg, g_cpg);
    float* h3;  cudaGetSymbolAddress((void**)&h3,  g_h3);
    float* h4;  cudaGetSymbolAddress((void**)&h4,  g_h4);

    // 1) h1 = relu(iW0 @ [x, ts] + ib0)   [4096 x 2049]
    matvec_l1<<<4096, 256>>>(iW0, ib0, x, ts, h1);

    // 2) h2 = relu(iW1 @ h1 + ib1)        [4096 x 4096]
    launch_pdl(matvec_b<true, 1024>, dim3(4096), dim3(256), iW1, ib1, h1, h2);

    // 3) params = iW2 @ h2 + ib2          [2112 x 4096]
    launch_pdl(matvec_b<false, 1024>, dim3(2112), dim3(256), iW2, ib2, h2, pr);

    // 4) RK4 step + cpg_out; writes new_state to d_out[0:96]
    launch_pdl(cpg_ode_kernel, dim3(1), dim3(1024), state, ts, out);

    // 5) h3 = relu(oW0 @ cpg + ob0)       [2048 x 64]
    launch_pdl(matvec_small64, dim3((2048 * 32) / 256), dim3(256), oW0, ob0, cpg, h3, 2048);

    // 6) h4 = relu(oW1 @ h3 + ob1)        [2048 x 2048]
    launch_pdl(matvec_b<true, 512>, dim3(2048), dim3(256), oW1, ob1, h3, h4);

    // 7) out = oW2 @ h4 + ob2             [1024 x 2048] -> d_out[96:1120]
    launch_pdl(matvec_b<false, 512>, dim3(1024), dim3(256), oW2, ob2, h4, out + 96);
}

// round 6
// speedup vs baseline: 1.7807x; 1.0154x over previous
#include <cuda_runtime.h>
#include <cuda_bf16.h>
#include <math.h>

#define N_OSC 32
#define CONVC 1000.0f

// -------- scratch (no allocations allowed) --------
__device__ float g_h1[4096];
__device__ float g_h2[4096];
__device__ float g_params[2112];
__device__ float g_cpg[64];
__device__ float g_h3[2048];
__device__ float g_h4[2048];

// ============ block-per-row matvec with PDL weight prefetch ============
template <bool RELU, int C4>
__global__ __launch_bounds__(256) void matvec_b(const float* __restrict__ W,
                                                const float* __restrict__ b,
                                                const float* __restrict__ x,
                                                float* __restrict__ y) {
    int row = blockIdx.x;
    const float4* __restrict__ w4 = reinterpret_cast<const float4*>(W) + (size_t)row * C4;
    const float4* __restrict__ x4 = reinterpret_cast<const float4*>(x);

    float4 wreg[C4 / 256];
    #pragma unroll
    for (int k = 0; k < C4 / 256; ++k)
        wreg[k] = w4[threadIdx.x + k * 256];
    float bias = (threadIdx.x == 0) ? b[row] : 0.f;

    cudaGridDependencySynchronize();   // wait for predecessor's x

    float s = 0.f;
    #pragma unroll
    for (int k = 0; k < C4 / 256; ++k) {
        float4 v = x4[threadIdx.x + k * 256];
        s += wreg[k].x * v.x + wreg[k].y * v.y + wreg[k].z * v.z + wreg[k].w * v.w;
    }

    #pragma unroll
    for (int o = 16; o; o >>= 1) s += __shfl_xor_sync(0xFFFFFFFFu, s, o);
    __shared__ float red[8];
    if ((threadIdx.x & 31) == 0) red[threadIdx.x >> 5] = s;
    __syncthreads();
    if (threadIdx.x < 8) {
        float v = red[threadIdx.x];
        #pragma unroll
        for (int o = 4; o; o >>= 1) v += __shfl_xor_sync(0xFFu, v, o);
        if (threadIdx.x == 0) {
            v += bias;
            if (RELU) v = fmaxf(v, 0.f);
            y[row] = v;
        }
    }
}

// ============ layer 1: cols = 2049 (2048 from x + timestep) ============
__global__ __launch_bounds__(256) void matvec_l1(const float* __restrict__ W,
                                                 const float* __restrict__ b,
                                                 const float* __restrict__ x,
                                                 const float* __restrict__ ts,
                                                 float* __restrict__ y) {
    int row = blockIdx.x;
    const float* __restrict__ w = W + (size_t)row * 2049;

    float s = 0.f;
    #pragma unroll
    for (int k = 0; k < 8; ++k) {
        int c = threadIdx.x + k * 256;
        s += w[c] * x[c];
    }
    if (threadIdx.x == 0) s += w[2048] * ts[0];

    #pragma unroll
    for (int o = 16; o; o >>= 1) s += __shfl_xor_sync(0xFFFFFFFFu, s, o);
    __shared__ float red[8];
    if ((threadIdx.x & 31) == 0) red[threadIdx.x >> 5] = s;
    __syncthreads();
    if (threadIdx.x < 8) {
        float v = red[threadIdx.x];
        #pragma unroll
        for (int o = 4; o; o >>= 1) v += __shfl_xor_sync(0xFFu, v, o);
        if (threadIdx.x == 0) {
            v += b[row];
            y[row] = fmaxf(v, 0.f);
        }
    }
}

// ============ small layer [2048 x 64]: warp-per-row, PDL prefetch ============
__global__ void matvec_small64(const float* __restrict__ W,
                               const float* __restrict__ b,
                               const float* __restrict__ x,
                               float* __restrict__ y, int rows) {
    int warp = (blockIdx.x * blockDim.x + threadIdx.x) >> 5;
    int lane = threadIdx.x & 31;

    float4 w = make_float4(0.f, 0.f, 0.f, 0.f);
    float bias = 0.f;
    if (warp < rows) {
        if (lane < 16)
            w = reinterpret_cast<const float4*>(W + (size_t)warp * 64)[lane];
        if (lane == 0) bias = b[warp];
    }

    cudaGridDependencySynchronize();   // wait for cpg

    if (warp >= rows) return;
    float s = 0.f;
    if (lane < 16) {
        float4 v = reinterpret_cast<const float4*>(x)[lane];
        s = w.x * v.x + w.y * v.y + w.z * v.z + w.w * v.w;
    }
    #pragma unroll
    for (int o = 8; o; o >>= 1) s += __shfl_xor_sync(0xFFFFFFFFu, s, o);
    if (lane == 0) y[warp] = fmaxf(s + bias, 0.f);
}

// ============ CPG ODE, RK4 3/8 rule — SINGLE WARP, registers + __sinf ============
// Lane i <-> oscillator i. Coupling row cw[i][:], pb[i][:] in registers.
// Only phases cross lanes, via s_ph[] (same-address LDS = broadcast).
// Replicates reference slicing exactly: phase_dots go into the a_dot slot,
// and post-step "ph" is read from that slot for cpg_out.
__global__ __launch_bounds__(32) void cpg_ode_kernel(
        const float* __restrict__ state,
        const float* __restrict__ ts,
        float* __restrict__ d_out_state /* 96 floats */) {
    __shared__ float s_ph[N_OSC];

    int i = threadIdx.x;   // lane = oscillator

    // independent inputs: prefetch before dependency sync
    float h   = ts[0];
    float ya  = state[i];
    float yad = state[N_OSC + i];
    float yph = state[2 * N_OSC + i];

    cudaGridDependencySynchronize();   // wait for g_params (layer-3 output)

    // per-lane coupling rows into registers (8+8 float4, per-lane contiguous,
    // warp-level fully coalesced: lanes cover 4KB contiguous each matrix)
    float cw[N_OSC], pb[N_OSC];
    {
        const float4* cw4 = reinterpret_cast<const float4*>(g_params + 2 * N_OSC) + i * 8;
        const float4* pb4 = reinterpret_cast<const float4*>(g_params + 2 * N_OSC + N_OSC * N_OSC) + i * 8;
        #pragma unroll
        for (int k = 0; k < 8; ++k) {
            float4 c = cw4[k];
            cw[4 * k + 0] = c.x; cw[4 * k + 1] = c.y; cw[4 * k + 2] = c.z; cw[4 * k + 3] = c.w;
            float4 p = pb4[k];
            pb[4 * k + 0] = p.x; pb[4 * k + 1] = p.y; pb[4 * k + 2] = p.z; pb[4 * k + 3] = p.w;
        }
    }
    float ia  = g_params[i];
    float ifr = g_params[N_OSC + i];

    float k1a, k1ad, k1ph, k2a, k2ad, k2ph, k3a, k3ad, k3ph, k4a, k4ad, k4ph;

    // f at eval point (ea, ead, eph) -> (ka, kad, kph), per lane
    auto stage = [&](float ea, float ead, float eph,
                     float& ka, float& kad, float& kph) {
        s_ph[i] = eph;
        __syncwarp();
        float t = 0.f;
        #pragma unroll
        for (int j = 0; j < N_OSC; ++j)
            t += cw[j] * __sinf(s_ph[j] - eph - pb[j]);
        __syncwarp();
        kad = ifr + ea * t;                                // phase_dots
        ka  = ead;                                         // a_dot
        kph = CONVC * (CONVC * 0.25f * (ia - ea) - ead);   // a_dd
    };

    // k1 at y
    stage(ya, yad, yph, k1a, k1ad, k1ph);
    // k2 at y + h*k1/3
    stage(ya + h * k1a / 3.0f, yad + h * k1ad / 3.0f, yph + h * k1ph / 3.0f,
          k2a, k2ad, k2ph);
    // k3 at y + h*(k2 - k1/3)
    stage(ya + h * (k2a - k1a / 3.0f),
          yad + h * (k2ad - k1ad / 3.0f),
          yph + h * (k2ph - k1ph / 3.0f),
          k3a, k3ad, k3ph);
    // k4 at y + h*(k1 - k2 + k3)
    stage(ya + h * (k1a - k2a + k3a),
          yad + h * (k1ad - k2ad + k3ad),
          yph + h * (k1ph - k2ph + k3ph),
          k4a, k4ad, k4ph);

    float yna  = ya  + h * 0.125f * (k1a  + 3.0f * (k2a  + k3a)  + k4a);
    float ynad = yad + h * 0.125f * (k1ad + 3.0f * (k2ad + k3ad) + k4ad);
    float ynph = yph + h * 0.125f * (k1ph + 3.0f * (k2ph + k3ph) + k4ph);

    d_out_state[i]             = yna;
    d_out_state[N_OSC + i]     = ynad;
    d_out_state[2 * N_OSC + i] = ynph;

    // reference reads ns[:n] as a and ns[n:2n] (the a_dot slot) as ph
    g_cpg[i]         = yna * __cosf(ynad);
    g_cpg[N_OSC + i] = yna * __sinf(ynad);
}

// -------- launch helper with PDL attribute --------
template <typename K, typename... Args>
static void launch_pdl(K kernel, dim3 grid, dim3 block, Args... args) {
    cudaLaunchConfig_t cfg = {};
    cfg.gridDim = grid;
    cfg.blockDim = block;
    cudaLaunchAttribute attr[1];
    attr[0].id = cudaLaunchAttributeProgrammaticStreamSerialization;
    attr[0].val.programmaticStreamSerializationAllowed = 1;
    cfg.attrs = attr;
    cfg.numAttrs = 1;
    cudaLaunchKernelEx(&cfg, kernel, args...);
}

extern "C" void kernel_launch(void* const* d_in, const int* in_sizes, int n_in,
                              void* d_out, int out_size) {
    const float* state = (const float*)d_in[0];
    const float* x     = (const float*)d_in[1];
    const float* ts    = (const float*)d_in[2];
    const float* iW0   = (const float*)d_in[3];
    const float* ib0   = (const float*)d_in[4];
    const float* iW1   = (const float*)d_in[5];
    const float* ib1   = (const float*)d_in[6];
    const float* iW2   = (const float*)d_in[7];
    const float* ib2   = (const float*)d_in[8];
    const float* oW0   = (const float*)d_in[9];
    const float* ob0   = (const float*)d_in[10];
    const float* oW1   = (const float*)d_in[11];
    const float* ob1   = (const float*)d_in[12];
    const float* oW2   = (const float*)d_in[13];
    const float* ob2   = (const float*)d_in[14];
    float* out = (float*)d_out;   // [new_state(96), out(1024)]

    float* h1;  cudaGetSymbolAddress((void**)&h1,  g_h1);
    float* h2;  cudaGetSymbolAddress((void**)&h2,  g_h2);
    float* pr;  cudaGetSymbolAddress((void**)&pr,  g_params);
    float* cpg; cudaGetSymbolAddress((void**)&cpg, g_cpg);
    float* h3;  cudaGetSymbolAddress((void**)&h3,  g_h3);
    float* h4;  cudaGetSymbolAddress((void**)&h4,  g_h4);

    // 1) h1 = relu(iW0 @ [x, ts] + ib0)   [4096 x 2049]
    matvec_l1<<<4096, 256>>>(iW0, ib0, x, ts, h1);

    // 2) h2 = relu(iW1 @ h1 + ib1)        [4096 x 4096]
    launch_pdl(matvec_b<true, 1024>, dim3(4096), dim3(256), iW1, ib1, h1, h2);

    // 3) params = iW2 @ h2 + ib2          [2112 x 4096]
    launch_pdl(matvec_b<false, 1024>, dim3(2112), dim3(256), iW2, ib2, h2, pr);

    // 4) RK4 step + cpg_out; writes new_state to d_out[0:96]
    launch_pdl(cpg_ode_kernel, dim3(1), dim3(32), state, ts, out);

    // 5) h3 = relu(oW0 @ cpg + ob0)       [2048 x 64]
    launch_pdl(matvec_small64, dim3((2048 * 32) / 256), dim3(256), oW0, ob0, cpg, h3, 2048);

    // 6) h4 = relu(oW1 @ h3 + ob1)        [2048 x 2048]
    launch_pdl(matvec_b<true, 512>, dim3(2048), dim3(256), oW1, ob1, h3, h4);

    // 7) out = oW2 @ h4 + ob2             [1024 x 2048] -> d_out[96:1120]
    launch_pdl(matvec_b<false, 512>, dim3(1024), dim3(256), oW2, ob2, h4, out + 96);
}